// round 14
// baseline (speedup 1.0000x reference)
#include <cuda_runtime.h>
#include <cuda_bf16.h>
#include <math.h>

// Wavefront SOS ray integration — locked numerics (rel_err ~4.06e-4):
//   index chain bit-identical to reference (XLA:CPU jit model):
//     t = fl(k*DELTA), lt = fl(l*t), xs = fl(x - fl(lt*sinth)), ys likewise,
//     jf = fl((xs-x0)*fl(1/dx)), if = fl((ylast-ys)*fl(1/dy)), cvt.rni
// perf (R14 = R13 + anti-fusion):
//   - packed f32x2 index chain, 2 samples/thread-iter (k, k+2048)
//   - ptxas contracted mul.rn.f32x2+add.rn.f32x2 into FFMA2 in R13 (error
//     signature matched the "fused xs/ys" term 2.5e-3 exactly). Negations are
//     now done with integer xor.b64 on the packed sign bits between the mul
//     and the add — real dataflow through the ALU pipe, unfusable, exact.
//   - geom kernel: f64 sincos, 128-thread blocks
//   - sum-of-reciprocals accumulation + endpoint correction

#define N_INT    4096
#define THREADS  256
#define MAX_RAYS 4096

__device__ float g_l[MAX_RAYS];
__device__ float g_sinth[MAX_RAYS];
__device__ float g_costh[MAX_RAYS];

// ---- packed f32x2 helpers ----
__device__ __forceinline__ unsigned long long pk2(float lo, float hi) {
    unsigned long long r;
    asm("mov.b64 %0, {%1, %2};" : "=l"(r) : "f"(lo), "f"(hi));
    return r;
}
__device__ __forceinline__ void upk2(unsigned long long v, float& lo, float& hi) {
    asm("mov.b64 {%0, %1}, %2;" : "=f"(lo), "=f"(hi) : "l"(v));
}
__device__ __forceinline__ unsigned long long mul2(unsigned long long a, unsigned long long b) {
    unsigned long long r;
    asm("mul.rn.f32x2 %0, %1, %2;" : "=l"(r) : "l"(a), "l"(b));
    return r;
}
__device__ __forceinline__ unsigned long long add2(unsigned long long a, unsigned long long b) {
    unsigned long long r;
    asm("add.rn.f32x2 %0, %1, %2;" : "=l"(r) : "l"(a), "l"(b));
    return r;
}
// exact packed negation via sign-bit xor; integer op -> blocks FMA contraction
__device__ __forceinline__ unsigned long long neg2(unsigned long long a) {
    unsigned long long r;
    asm("xor.b64 %0, %1, 0x8000000080000000;" : "=l"(r) : "l"(a));
    return r;
}

// ---------- kernel A: per-ray geometry (CR f32 via f64 sincos) ----------
__global__ void geom_kernel(const float* __restrict__ xp,
                            const float* __restrict__ yp,
                            const float* __restrict__ thetas,
                            const float* __restrict__ Rp,
                            int n_points)
{
    const int ray = blockIdx.x * blockDim.x + threadIdx.x;
    if (ray >= n_points) return;

    const float th = thetas[ray];
    const float x  = xp[0];
    const float y  = yp[0];
    const float R  = Rp[0];

    double sth_d, cth_d;
    sincos((double)th, &sth_d, &cth_d);

    const float r   = __fsqrt_rn(__fadd_rn(__fmul_rn(x, x), __fmul_rn(y, y)));
    const float phi = (float)atan2((double)x, (double)y);   // reference: arctan2(x, y)
    const float d   = __fsub_rn(th, phi);

    double sd_d, cd_d;
    sincos((double)d, &sd_d, &cd_d);

    const float s    = __fmul_rn(r, (float)sd_d);
    const float c    = __fmul_rn(r, (float)cd_d);
    const float disc = __fsub_rn(__fmul_rn(R, R), __fmul_rn(s, s));

    float l;
    if (r < R) {
        l = __fadd_rn(__fsqrt_rn(fmaxf(disc, 0.0f)), c);
    } else {
        const float pmt  = __fsub_rn(phi, th);
        const bool  mask = ((float)cos((double)pmt) >= 0.0f) && (R >= fabsf(s));
        const float dm = mask ? disc : 0.0f;
        const float cm = mask ? c    : 0.0f;
        l = __fadd_rn(__fsqrt_rn(fmaxf(dm, 0.0f)), cm);
    }

    g_l[ray]     = l;
    g_sinth[ray] = (float)sth_d;
    g_costh[ray] = (float)cth_d;
}

// ---------- kernel B: ray integration (packed f32x2, anti-fused) ----------
__global__ __launch_bounds__(THREADS)
void integrate_kernel(const float* __restrict__ xp,
                      const float* __restrict__ yp,
                      const float* __restrict__ SOS,
                      const float* __restrict__ x_vec,
                      const float* __restrict__ y_vec,
                      const float* __restrict__ thetas,
                      const float* __restrict__ v0p,
                      float* __restrict__ out,
                      int n_grid, int n_points, int out_size)
{
    const int ray  = blockIdx.x;
    const int lane = threadIdx.x & 31;
    const int warp = threadIdx.x >> 5;

    const float x  = xp[0];
    const float y  = yp[0];
    const float v0 = v0p[0];

    const float x0    = x_vec[0];
    const float dx    = __fsub_rn(x_vec[1], x_vec[0]);
    const float ylast = y_vec[n_grid - 1];
    const float dy    = __fsub_rn(y_vec[1], y_vec[0]);

    // XLA divide rewrite: scalar reciprocals (one CR division each)
    const float rdx = __fdiv_rn(1.0f, dx);
    const float rdy = __fdiv_rn(1.0f, dy);

    const float l     = g_l[ray];
    const float sinth = g_sinth[ray];
    const float costh = g_costh[ray];

    const float DELTA = 1.0f / 4095.0f;   // fl(1/(N_INT-1)); steps_k = fl(k*DELTA)

    // scalar sampler for endpoint correction (bit-exact chain)
    auto sample_S = [&](float kff) -> float {
        const float t  = __fmul_rn(kff, DELTA);
        const float lt = __fmul_rn(l, t);
        const float xs = __fsub_rn(x, __fmul_rn(lt, sinth));
        const float ys = __fsub_rn(y, __fmul_rn(lt, costh));
        const float jf  = __fmul_rn(__fsub_rn(xs, x0), rdx);
        const float if_ = __fmul_rn(__fsub_rn(ylast, ys), rdy);
        const int j = __float2int_rn(jf);
        const int i = __float2int_rn(if_);
        return __ldg(&SOS[i * n_grid + j]);
    };

    // packed constants (block-uniform)
    const unsigned long long DELTA2  = pk2(DELTA, DELTA);
    const unsigned long long L2      = pk2(l, l);
    const unsigned long long SIN2    = pk2(sinth, sinth);
    const unsigned long long COS2    = pk2(costh, costh);
    const unsigned long long X2      = pk2(x, x);
    const unsigned long long Y2      = pk2(y, y);
    const unsigned long long MX02    = pk2(-x0, -x0);
    const unsigned long long YLAST2  = pk2(ylast, ylast);
    const unsigned long long RDX2    = pk2(rdx, rdx);
    const unsigned long long RDY2    = pk2(rdy, rdy);
    const unsigned long long STEP2   = pk2(32.0f, 32.0f);

    // pair mapping: lo half kA in [0,2048), hi half kB = kA + 2048.
    // warp w covers kA in [w*256, (w+1)*256), lane-strided (coalesced).
    const float kA0 = (float)(warp * (N_INT / 2 / (THREADS / 32)) + lane);
    unsigned long long kf2 = pk2(kA0, kA0 + (float)(N_INT / 2));

    float accA = 0.0f, accB = 0.0f;   // sums of rcp(S)

    #pragma unroll
    for (int it = 0; it < (N_INT / 2 / THREADS); it++) {   // 8 iters
        const unsigned long long t2  = mul2(kf2, DELTA2);
        const unsigned long long lt2 = mul2(L2, t2);

        // xs = fl(x - fl(lt*sinth)): mul, xor-negate, add (two roundings)
        const unsigned long long msx = neg2(mul2(lt2, SIN2));
        const unsigned long long xs2 = add2(X2, msx);
        const unsigned long long jf2 = mul2(add2(xs2, MX02), RDX2);

        // ys = fl(y - fl(lt*costh)); d = fl(ylast - ys)
        const unsigned long long msy = neg2(mul2(lt2, COS2));
        const unsigned long long ys2 = add2(Y2, msy);
        const unsigned long long if2 = mul2(add2(YLAST2, neg2(ys2)), RDY2);

        float jfA, jfB, ifA, ifB;
        upk2(jf2, jfA, jfB);
        upk2(if2, ifA, ifB);

        const int jA = __float2int_rn(jfA);
        const int iA = __float2int_rn(ifA);
        const int jB = __float2int_rn(jfB);
        const int iB = __float2int_rn(ifB);

        const float SA = __ldg(&SOS[iA * n_grid + jA]);
        const float SB = __ldg(&SOS[iB * n_grid + jB]);

        float rA, rB;
        asm("rcp.approx.f32 %0, %1;" : "=f"(rA) : "f"(SA));
        asm("rcp.approx.f32 %0, %1;" : "=f"(rB) : "f"(SB));
        accA = __fadd_rn(accA, rA);
        accB = __fadd_rn(accB, rB);

        kf2 = add2(kf2, STEP2);
    }

    float acc = __fadd_rn(accA, accB);

    // ---- block reduction of sum(rcp(S)) ----
    __shared__ float red[THREADS / 32];
    #pragma unroll
    for (int o = 16; o > 0; o >>= 1)
        acc += __shfl_down_sync(0xFFFFFFFFu, acc, o);
    if (lane == 0)
        red[warp] = acc;
    __syncthreads();

    if (threadIdx.x == 0) {
        float Q = 0.0f;
        #pragma unroll
        for (int w = 0; w < THREADS / 32; w++)
            Q += red[w];

        // sum_k f_k = N_INT - v0 * Q ; endpoints carry half weight
        const float S0 = sample_S(0.0f);
        const float SN = sample_S((float)(N_INT - 1));
        const float f0 = __fsub_rn(1.0f, __fdividef(v0, S0));
        const float fN = __fsub_rn(1.0f, __fdividef(v0, SN));

        const float sumf = __fsub_rn((float)N_INT, __fmul_rn(v0, Q));
        const float ld   = __fmul_rn(l, DELTA);
        const float wf   = __fmul_rn(ld, __fsub_rn(sumf,
                                __fmul_rn(0.5f, __fadd_rn(f0, fN))));

        if (out_size >= 2 * n_points) {
            out[ray]            = thetas[ray];  // output[0]: thetas passthrough
            out[n_points + ray] = wf;           // output[1]: wf
        } else {
            out[ray] = wf;
        }
    }
}

extern "C" void kernel_launch(void* const* d_in, const int* in_sizes, int n_in,
                              void* d_out, int out_size)
{
    const float* x      = (const float*)d_in[0];
    const float* y      = (const float*)d_in[1];
    const float* SOS    = (const float*)d_in[2];
    const float* x_vec  = (const float*)d_in[3];
    const float* y_vec  = (const float*)d_in[4];
    const float* thetas = (const float*)d_in[5];
    const float* Rb     = (const float*)d_in[6];
    const float* v0     = (const float*)d_in[7];

    const int n_grid   = in_sizes[3];   // 4096
    const int n_points = in_sizes[5];   // 2048

    geom_kernel<<<(n_points + 127) / 128, 128>>>(x, y, thetas, Rb, n_points);
    integrate_kernel<<<n_points, THREADS>>>(
        x, y, SOS, x_vec, y_vec, thetas, v0,
        (float*)d_out, n_grid, n_points, out_size);
}